// round 4
// baseline (speedup 1.0000x reference)
#include <cuda_runtime.h>
#include <math.h>

#define N_ROWS 48000
#define DIMS   256
#define KCODES 1024
#define GK     64

#define BM 64          // rows per CTA
#define BN 64          // codes per tile
#define DC 32          // d-chunk for cb staging (double-buffered)
#define XP 66          // xs pitch (words) for transposed [d][row] tile; even -> LDS.64 aligned
#define CBW (DC*BN)    // words per cb chunk buffer
#define DECAYF 0.99f
#define OMDF   0.01f
#define EPSF   1e-5f

typedef unsigned long long ull;

// ---------------- scratch (no allocation allowed) ----------------
__device__ float g_shape_sum[KCODES * DIMS];
__device__ float g_shape_cnt[KCODES];
__device__ float g_gain_sum[GK];
__device__ float g_gain_cnt[GK];

__global__ void init_kernel() {
    int i = blockIdx.x * blockDim.x + threadIdx.x;
    if (i < KCODES * DIMS) g_shape_sum[i] = 0.f;
    if (i < KCODES)        g_shape_cnt[i] = 0.f;
    if (i < GK)  { g_gain_sum[i] = 0.f; g_gain_cnt[i] = 0.f; }
}

// ---------------- packed fp32x2 helpers ----------------
__device__ __forceinline__ ull pack2(float a, float b) {
    ull r; asm("mov.b64 %0, {%1,%2};" : "=l"(r) : "f"(a), "f"(b)); return r;
}
__device__ __forceinline__ void unpack2(ull v, float& lo, float& hi) {
    asm("mov.b64 {%0,%1}, %2;" : "=f"(lo), "=f"(hi) : "l"(v));
}
__device__ __forceinline__ void ffma2(ull& d, ull a, ull b) {
    asm("fma.rn.f32x2 %0, %1, %2, %0;" : "+l"(d) : "l"(a), "l"(b));
}

// stage one 32d x 64c cb chunk, transposed to [dl][c], into buf (conflict-free)
__device__ __forceinline__ void stage_cb(const float* __restrict__ cb,
                                         float* __restrict__ dst,
                                         int q, int tid) {
    int c  = tid & 63;
    int dg = tid >> 6;                   // 0..3
    int ct = q >> 3;                     // code tile
    int dcc = q & 7;                     // d chunk within dims
    const float* src = cb + (size_t)(ct * BN + c) * DIMS + dcc * DC;
    #pragma unroll
    for (int w = 0; w < 2; w++) {
        int dloc = dg * 8 + w * 4;
        float4 v = *(const float4*)(src + dloc);
        dst[(dloc + 0) * BN + c] = v.x;
        dst[(dloc + 1) * BN + c] = v.y;
        dst[(dloc + 2) * BN + c] = v.z;
        dst[(dloc + 3) * BN + c] = v.w;
    }
}

// ---------------- main: GEMM(f32x2) + argmax + gain quant + scatter ----------
__global__ __launch_bounds__(256) void vq_main(
    const float* __restrict__ x,
    const float* __restrict__ cb,
    const float* __restrict__ gcb,
    float* __restrict__ out_q)
{
    extern __shared__ float sm[];
    float* xs    = sm;                      // [256][XP]  transposed: xs[d*XP + r]
    float* cbs   = xs + DIMS * XP;          // 2 x [DC][BN]
    float* gains = cbs + 2 * CBW;           // [64]
    float* bval  = gains + GK;              // [64]
    int*   bidx  = (int*)(bval + BM);       // [64]
    float* bscale= (float*)(bidx + BM);     // [64]

    const int tid = threadIdx.x;
    const int row0 = blockIdx.x * BM;
    const int tx = tid & 15;      // code group 0..15 (4 codes each)
    const int ty = tid >> 4;      // row group 0..15 (4 rows each)

    // ---- stage x tile TRANSPOSED: xs[d][r] ----
    {
        int r = tid & 63;                // row
        int g = tid >> 6;                // 0..3 d-quarter
        #pragma unroll
        for (int p = 0; p < 16; p++) {
            int d4 = g * 64 + p * 4;
            float4 v = *(const float4*)(x + (size_t)(row0 + r) * DIMS + d4);
            xs[(d4 + 0) * XP + r] = v.x;
            xs[(d4 + 1) * XP + r] = v.y;
            xs[(d4 + 2) * XP + r] = v.z;
            xs[(d4 + 3) * XP + r] = v.w;
        }
    }
    if (tid < GK) gains[tid] = gcb[tid];

    // stage first cb chunk
    stage_cb(cb, cbs, 0, tid);
    __syncthreads();

    ull acc[4][2];   // [code j][row pair p]: p=0 -> rows (0,1), p=1 -> rows (2,3)
    #pragma unroll
    for (int j = 0; j < 4; j++) { acc[j][0] = 0ULL; acc[j][1] = 0ULL; }

    float runv[4]; int runi[4];
    #pragma unroll
    for (int i = 0; i < 4; i++) { runv[i] = -3.4e38f; runi[i] = 0; }

    const int NCHUNK = (KCODES / BN) * (DIMS / DC);   // 128
    for (int q = 0; q < NCHUNK; q++) {
        if (q + 1 < NCHUNK)
            stage_cb(cb, cbs + ((q + 1) & 1) * CBW, q + 1, tid);

        const float* cbuf = cbs + (q & 1) * CBW;
        const int dbase = (q & 7) * DC;
        const float* xbase = xs + dbase * XP + ty * 4;

        #pragma unroll 4
        for (int dl = 0; dl < DC; dl++) {
            ull xp0 = *(const ull*)(xbase + dl * XP);       // rows r0, r0+1
            ull xp1 = *(const ull*)(xbase + dl * XP + 2);   // rows r0+2, r0+3
            float4 cv = *(const float4*)(cbuf + dl * BN + (tx << 2));
            ull c0 = pack2(cv.x, cv.x);
            ull c1 = pack2(cv.y, cv.y);
            ull c2 = pack2(cv.z, cv.z);
            ull c3 = pack2(cv.w, cv.w);
            ffma2(acc[0][0], xp0, c0); ffma2(acc[0][1], xp1, c0);
            ffma2(acc[1][0], xp0, c1); ffma2(acc[1][1], xp1, c1);
            ffma2(acc[2][0], xp0, c2); ffma2(acc[2][1], xp1, c2);
            ffma2(acc[3][0], xp0, c3); ffma2(acc[3][1], xp1, c3);
        }

        if ((q & 7) == 7) {
            // tile done: unpack accumulators -> av[row i][code j]
            int ct = q >> 3;
            float av[4][4];
            #pragma unroll
            for (int j = 0; j < 4; j++) {
                unpack2(acc[j][0], av[0][j], av[1][j]);
                unpack2(acc[j][1], av[2][j], av[3][j]);
                acc[j][0] = 0ULL; acc[j][1] = 0ULL;
            }
            #pragma unroll
            for (int i = 0; i < 4; i++) {
                float bv = av[i][0]; int bj = 0;
                if (av[i][1] > bv) { bv = av[i][1]; bj = 1; }
                if (av[i][2] > bv) { bv = av[i][2]; bj = 2; }
                if (av[i][3] > bv) { bv = av[i][3]; bj = 3; }
                int bc = ct * BN + tx * 4 + bj;
                #pragma unroll
                for (int off = 1; off < 16; off <<= 1) {
                    float ov = __shfl_xor_sync(0xffffffffu, bv, off);
                    int   oc = __shfl_xor_sync(0xffffffffu, bc, off);
                    if (ov > bv || (ov == bv && oc < bc)) { bv = ov; bc = oc; }
                }
                if (bv > runv[i]) { runv[i] = bv; runi[i] = bc; }
            }
        }
        __syncthreads();
    }

    if (tx == 0) {
        #pragma unroll
        for (int i = 0; i < 4; i++) {
            bval[ty * 4 + i] = runv[i];
            bidx[ty * 4 + i] = runi[i];
        }
    }
    __syncthreads();

    // ---- gain quantization + scalar stats (one thread per row) ----
    if (tid < BM) {
        float g = logf(fmaxf(bval[tid], EPSF));   // LOG_GAIN, clip min EPS
        float bd = 3.4e38f; int gi = 0;
        #pragma unroll
        for (int j = 0; j < GK; j++) {
            float d = g - gains[j];
            float d2 = d * d;
            if (d2 < bd) { bd = d2; gi = j; }     // first-min == first argmax of -d2
        }
        atomicAdd(&g_gain_sum[gi], g);
        atomicAdd(&g_gain_cnt[gi], 1.f);
        atomicAdd(&g_shape_cnt[bidx[tid]], 1.f);
        bscale[tid] = expf(gains[gi]);            // exp(gain_q)
    }
    __syncthreads();

    // ---- epilogue: quantize output + shape_sum scatter ----
    for (int r = 0; r < BM; r++) {
        int k = bidx[r];
        float sc = bscale[r];
        float cv = cb[(size_t)k * DIMS + tid];
        out_q[(size_t)(row0 + r) * DIMS + tid] = sc * cv;
        atomicAdd(&g_shape_sum[(size_t)k * DIMS + tid],
                  x[(size_t)(row0 + r) * DIMS + tid]);
    }
}

// ---------------- finalize: EMA updates ----------------
__device__ __forceinline__ float blockSum256(float v, float* red) {
    __syncthreads();
    int lane = threadIdx.x & 31, w = threadIdx.x >> 5;
    #pragma unroll
    for (int o = 16; o; o >>= 1) v += __shfl_xor_sync(0xffffffffu, v, o);
    if (lane == 0) red[w] = v;
    __syncthreads();
    if (w == 0) {
        float t = (lane < 8) ? red[lane] : 0.f;
        #pragma unroll
        for (int o = 4; o; o >>= 1) t += __shfl_xor_sync(0xffffffffu, t, o);
        if (lane == 0) red[0] = t;
    }
    __syncthreads();
    return red[0];
}

__global__ __launch_bounds__(256) void vq_finalize(
    const float* __restrict__ cb,   const float* __restrict__ gcb,
    const float* __restrict__ snum, const float* __restrict__ gnum,
    float* __restrict__ out_shape,  float* __restrict__ out_gain,
    float* __restrict__ out_snum,   float* __restrict__ out_gnum)
{
    __shared__ float red[8];
    int k = blockIdx.x, t = threadIdx.x;

    float s = g_shape_sum[k * DIMS + t];
    float ss = blockSum256(s * s, red);
    float denom = fmaxf(sqrtf(ss), EPSF);             // clip(norm, EPS)
    float upd = cb[k * DIMS + t] * DECAYF + (s / denom) * OMDF;
    float nn = blockSum256(upd * upd, red);
    float n2 = fmaxf(sqrtf(nn), 1e-12f);              // _l2norm clip 1e-12
    out_shape[k * DIMS + t] = upd / n2;

    if (t == 0)
        out_snum[k] = snum[k] * DECAYF + g_shape_cnt[k] * OMDF;

    if (k == 0 && t < GK) {
        float cnt  = g_gain_cnt[t];
        float gnew = g_gain_sum[t] / fmaxf(cnt, EPSF);
        out_gain[t] = gcb[t]  * DECAYF + gnew * OMDF;
        out_gnum[t] = gnum[t] * DECAYF + cnt  * OMDF;
    }
}

// ---------------- launch ----------------
extern "C" void kernel_launch(void* const* d_in, const int* in_sizes, int n_in,
                              void* d_out, int out_size) {
    const float* x    = (const float*)d_in[0];   // (48000, 256)
    const float* cb   = (const float*)d_in[1];   // (1024, 256)
    const float* gcb  = (const float*)d_in[2];   // (64,)
    const float* snum = (const float*)d_in[3];   // (1024,)
    const float* gnum = (const float*)d_in[4];   // (64,)

    float* out       = (float*)d_out;
    float* out_q     = out;                             // 12,288,000
    float* out_shape = out_q + (size_t)N_ROWS * DIMS;   // 262,144
    float* out_gain  = out_shape + KCODES * DIMS;       // 64
    float* out_snum  = out_gain + GK;                   // 1024
    float* out_gnum  = out_snum + KCODES;               // 64

    init_kernel<<<(KCODES * DIMS + 255) / 256, 256>>>();

    size_t smem = (size_t)(DIMS * XP + 2 * CBW + GK + BM + BM + BM) * 4;
    cudaFuncSetAttribute(vq_main, cudaFuncAttributeMaxDynamicSharedMemorySize,
                         (int)smem);
    vq_main<<<N_ROWS / BM, 256, smem>>>(x, cb, gcb, out_q);

    vq_finalize<<<KCODES, 256>>>(cb, gcb, snum, gnum,
                                 out_shape, out_gain, out_snum, out_gnum);
}